// round 10
// baseline (speedup 1.0000x reference)
#include <cuda_runtime.h>
#include <cuda_bf16.h>

#define NB_BATCH 16
#define NB_NH    32
#define NB_KVH   8
#define NB_NREP  4
#define NB_HD    128
#define NB_SCALE 0.08838834764831845f
#define NB_BPS   256
#define NB_NSPLIT 16
#define NB_CHUNK  256

// split-KV partial scratch (device globals: allocation-free)
__device__ float g_pacc[NB_BATCH * NB_KVH * NB_NSPLIT * NB_NREP * NB_HD]; // 4 MB
__device__ float g_pm[NB_BATCH * NB_KVH * NB_NSPLIT * NB_NREP];
__device__ float g_pl[NB_BATCH * NB_KVH * NB_NSPLIT * NB_NREP];
__device__ int   g_cnt[NB_BATCH * NB_KVH];   // zero-init; reset by reducer CTA

__global__ __launch_bounds__(256) void attn_split(
    const float* __restrict__ q,
    const float* __restrict__ kn,
    const float* __restrict__ vn,
    const float* __restrict__ kc,
    const float* __restrict__ vc,
    const int* __restrict__ bt,
    const int* __restrict__ ctx,
    const int* __restrict__ slotmap,
    float* __restrict__ out)
{
    const int split = blockIdx.x, g = blockIdx.y, b = blockIdx.z;
    const int bg = b * NB_KVH + g;
    const int cl = ctx[b];
    const int j0 = split * NB_CHUNK;
    const bool active = (j0 < cl);

    __shared__ int   sbt[16];
    __shared__ int   sslot[16];
    __shared__ const float* kptr[NB_CHUNK];
    __shared__ const float* vptr[NB_CHUNK];
    __shared__ float4 sp[NB_CHUNK];
    __shared__ float wred[8][4];
    __shared__ float smx[4];
    __shared__ float wacc[8][NB_NREP][NB_HD];
    __shared__ int   s_old;
    __shared__ float rM[4], rL[4], rE[4][NB_NSPLIT];

    const int tid = threadIdx.x;
    const int w = tid >> 5, lane = tid & 31;

    if (active) {
        const int vcnt = min(NB_CHUNK, cl - j0);

        if (tid < 16) {
            sbt[tid]   = bt[b * NB_BPS + split * 16 + tid];
            sslot[tid] = slotmap[tid];
        }
        __syncthreads();
        {   // per-token resolved pointers — valid for ALL 256 t regardless of vcnt
            const int t = tid;
            const int s = sbt[t >> 4] * 16 + (t & 15);
            int ov = -1;
            #pragma unroll
            for (int bp = 0; bp < NB_BATCH; bp++)
                if (sslot[bp] == s) ov = bp;     // last match wins
            const size_t crow = ((size_t)s * NB_KVH + g) * NB_HD;
            const size_t nrow = ((size_t)((ov >= 0) ? ov : 0) * NB_KVH + g) * NB_HD;
            kptr[t] = (ov >= 0) ? (kn + nrow) : (kc + crow);
            vptr[t] = (ov >= 0) ? (vn + nrow) : (vc + crow);
        }
        __syncthreads();

        // uniform padded trip count (multiple of 4); overshoot tokens are
        // masked at softmax (e=0) so both passes run branch-free.
        const int nt4 = (((vcnt + 7) >> 3) + 3) & ~3;

        // ---- Pass 1: scores (K stream), 4 batched LDG.128 per group ----
        {
            const float* qb = q + ((size_t)b * NB_NH + g * NB_NREP) * NB_HD + lane * 4;
            const float4 q0 = *(const float4*)(qb + 0 * NB_HD);
            const float4 q1 = *(const float4*)(qb + 1 * NB_HD);
            const float4 q2 = *(const float4*)(qb + 2 * NB_HD);
            const float4 q3 = *(const float4*)(qb + 3 * NB_HD);
            const bool b0 = (lane & 1) != 0;
            const bool b1 = (lane & 2) != 0;
            const int hm = ((lane & 1) << 1) | ((lane >> 1) & 1);

            #pragma unroll 1
            for (int i = 0; i < nt4; i += 4) {
                const int t0 = (i + 0) * 8 + w;
                const int t1 = (i + 1) * 8 + w;
                const int t2 = (i + 2) * 8 + w;
                const int t3 = (i + 3) * 8 + w;
                // batched loads (all independent, front-issued)
                const float4 k0 = *(const float4*)(kptr[t0] + lane * 4);
                const float4 k1 = *(const float4*)(kptr[t1] + lane * 4);
                const float4 k2 = *(const float4*)(kptr[t2] + lane * 4);
                const float4 k3 = *(const float4*)(kptr[t3] + lane * 4);

                float s[4][4];
                {
                    const float4 kk[4] = {k0, k1, k2, k3};
                    #pragma unroll
                    for (int j = 0; j < 4; j++) {
                        s[j][0] = fmaf(q0.x, kk[j].x, fmaf(q0.y, kk[j].y, fmaf(q0.z, kk[j].z, q0.w * kk[j].w)));
                        s[j][1] = fmaf(q1.x, kk[j].x, fmaf(q1.y, kk[j].y, fmaf(q1.z, kk[j].z, q1.w * kk[j].w)));
                        s[j][2] = fmaf(q2.x, kk[j].x, fmaf(q2.y, kk[j].y, fmaf(q2.z, kk[j].z, q2.w * kk[j].w)));
                        s[j][3] = fmaf(q3.x, kk[j].x, fmaf(q3.y, kk[j].y, fmaf(q3.z, kk[j].z, q3.w * kk[j].w)));
                    }
                }
                // 4 independent shfl reduction trees (6 shfl each)
                float bb[4];
                #pragma unroll
                for (int j = 0; j < 4; j++) {
                    float u  = b0 ? s[j][0] : s[j][2];
                    float vS = b0 ? s[j][1] : s[j][3];
                    float ru = __shfl_xor_sync(0xffffffffu, u, 1);
                    float rv = __shfl_xor_sync(0xffffffffu, vS, 1);
                    float a0 = (b0 ? s[j][2] : s[j][0]) + ru;
                    float a1 = (b0 ? s[j][3] : s[j][1]) + rv;
                    float ub = b1 ? a0 : a1;
                    float rb = __shfl_xor_sync(0xffffffffu, ub, 2);
                    bb[j] = (b1 ? a1 : a0) + rb;
                }
                #pragma unroll
                for (int j = 0; j < 4; j++) {
                    bb[j] += __shfl_xor_sync(0xffffffffu, bb[j], 4);
                    bb[j] += __shfl_xor_sync(0xffffffffu, bb[j], 8);
                    bb[j] += __shfl_xor_sync(0xffffffffu, bb[j], 16);
                }
                if (lane < 4) {
                    ((float*)&sp[t0])[hm] = bb[0] * NB_SCALE;
                    ((float*)&sp[t1])[hm] = bb[1] * NB_SCALE;
                    ((float*)&sp[t2])[hm] = bb[2] * NB_SCALE;
                    ((float*)&sp[t3])[hm] = bb[3] * NB_SCALE;
                }
            }
        }
        __syncthreads();

        // ---- Block softmax over the chunk ----
        {
            const int t = tid;
            float4 s4 = sp[t];
            if (t >= vcnt) { s4.x = s4.y = s4.z = s4.w = -1e30f; }
            float m0 = s4.x, m1 = s4.y, m2 = s4.z, m3 = s4.w;
            #pragma unroll
            for (int off = 16; off >= 1; off >>= 1) {
                m0 = fmaxf(m0, __shfl_xor_sync(0xffffffffu, m0, off));
                m1 = fmaxf(m1, __shfl_xor_sync(0xffffffffu, m1, off));
                m2 = fmaxf(m2, __shfl_xor_sync(0xffffffffu, m2, off));
                m3 = fmaxf(m3, __shfl_xor_sync(0xffffffffu, m3, off));
            }
            if (lane == 0) { wred[w][0] = m0; wred[w][1] = m1; wred[w][2] = m2; wred[w][3] = m3; }
            __syncthreads();
            if (tid < 4) {
                float mm = wred[0][tid];
                #pragma unroll
                for (int ww = 1; ww < 8; ww++) mm = fmaxf(mm, wred[ww][tid]);
                smx[tid] = mm;
            }
            __syncthreads();
            const float M0 = smx[0], M1 = smx[1], M2 = smx[2], M3 = smx[3];
            float e0 = 0.f, e1 = 0.f, e2 = 0.f, e3 = 0.f;
            if (t < vcnt) {
                e0 = __expf(s4.x - M0); e1 = __expf(s4.y - M1);
                e2 = __expf(s4.z - M2); e3 = __expf(s4.w - M3);
            }
            sp[t] = make_float4(e0, e1, e2, e3);
            #pragma unroll
            for (int off = 16; off >= 1; off >>= 1) {
                e0 += __shfl_xor_sync(0xffffffffu, e0, off);
                e1 += __shfl_xor_sync(0xffffffffu, e1, off);
                e2 += __shfl_xor_sync(0xffffffffu, e2, off);
                e3 += __shfl_xor_sync(0xffffffffu, e3, off);
            }
            if (lane == 0) { wred[w][0] = e0; wred[w][1] = e1; wred[w][2] = e2; wred[w][3] = e3; }
            __syncthreads();
            if (tid < 4) {
                float ss = wred[0][tid];
                #pragma unroll
                for (int ww = 1; ww < 8; ww++) ss += wred[ww][tid];
                const size_t pidx = ((size_t)bg * NB_NSPLIT + split) * NB_NREP + tid;
                g_pm[pidx] = smx[tid];
                g_pl[pidx] = ss;
            }
            __syncthreads();
        }

        // ---- Pass 2: output accumulation (V stream), batched loads ----
        {
            float4 a0 = make_float4(0.f,0.f,0.f,0.f), a1 = a0, a2 = a0, a3 = a0;
            #pragma unroll 1
            for (int i = 0; i < nt4; i += 4) {
                const int t0 = (i + 0) * 8 + w;
                const int t1 = (i + 1) * 8 + w;
                const int t2 = (i + 2) * 8 + w;
                const int t3 = (i + 3) * 8 + w;
                const float4 v0 = *(const float4*)(vptr[t0] + lane * 4);
                const float4 v1 = *(const float4*)(vptr[t1] + lane * 4);
                const float4 v2 = *(const float4*)(vptr[t2] + lane * 4);
                const float4 v3 = *(const float4*)(vptr[t3] + lane * 4);
                {
                    const float4 p = sp[t0];
                    a0.x = fmaf(p.x, v0.x, a0.x); a0.y = fmaf(p.x, v0.y, a0.y);
                    a0.z = fmaf(p.x, v0.z, a0.z); a0.w = fmaf(p.x, v0.w, a0.w);
                    a1.x = fmaf(p.y, v0.x, a1.x); a1.y = fmaf(p.y, v0.y, a1.y);
                    a1.z = fmaf(p.y, v0.z, a1.z); a1.w = fmaf(p.y, v0.w, a1.w);
                    a2.x = fmaf(p.z, v0.x, a2.x); a2.y = fmaf(p.z, v0.y, a2.y);
                    a2.z = fmaf(p.z, v0.z, a2.z); a2.w = fmaf(p.z, v0.w, a2.w);
                    a3.x = fmaf(p.w, v0.x, a3.x); a3.y = fmaf(p.w, v0.y, a3.y);
                    a3.z = fmaf(p.w, v0.z, a3.z); a3.w = fmaf(p.w, v0.w, a3.w);
                }
                {
                    const float4 p = sp[t1];
                    a0.x = fmaf(p.x, v1.x, a0.x); a0.y = fmaf(p.x, v1.y, a0.y);
                    a0.z = fmaf(p.x, v1.z, a0.z); a0.w = fmaf(p.x, v1.w, a0.w);
                    a1.x = fmaf(p.y, v1.x, a1.x); a1.y = fmaf(p.y, v1.y, a1.y);
                    a1.z = fmaf(p.y, v1.z, a1.z); a1.w = fmaf(p.y, v1.w, a1.w);
                    a2.x = fmaf(p.z, v1.x, a2.x); a2.y = fmaf(p.z, v1.y, a2.y);
                    a2.z = fmaf(p.z, v1.z, a2.z); a2.w = fmaf(p.z, v1.w, a2.w);
                    a3.x = fmaf(p.w, v1.x, a3.x); a3.y = fmaf(p.w, v1.y, a3.y);
                    a3.z = fmaf(p.w, v1.z, a3.z); a3.w = fmaf(p.w, v1.w, a3.w);
                }
                {
                    const float4 p = sp[t2];
                    a0.x = fmaf(p.x, v2.x, a0.x); a0.y = fmaf(p.x, v2.y, a0.y);
                    a0.z = fmaf(p.x, v2.z, a0.z); a0.w = fmaf(p.x, v2.w, a0.w);
                    a1.x = fmaf(p.y, v2.x, a1.x); a1.y = fmaf(p.y, v2.y, a1.y);
                    a1.z = fmaf(p.y, v2.z, a1.z); a1.w = fmaf(p.y, v2.w, a1.w);
                    a2.x = fmaf(p.z, v2.x, a2.x); a2.y = fmaf(p.z, v2.y, a2.y);
                    a2.z = fmaf(p.z, v2.z, a2.z); a2.w = fmaf(p.z, v2.w, a2.w);
                    a3.x = fmaf(p.w, v2.x, a3.x); a3.y = fmaf(p.w, v2.y, a3.y);
                    a3.z = fmaf(p.w, v2.z, a3.z); a3.w = fmaf(p.w, v2.w, a3.w);
                }
                {
                    const float4 p = sp[t3];
                    a0.x = fmaf(p.x, v3.x, a0.x); a0.y = fmaf(p.x, v3.y, a0.y);
                    a0.z = fmaf(p.x, v3.z, a0.z); a0.w = fmaf(p.x, v3.w, a0.w);
                    a1.x = fmaf(p.y, v3.x, a1.x); a1.y = fmaf(p.y, v3.y, a1.y);
                    a1.z = fmaf(p.y, v3.z, a1.z); a1.w = fmaf(p.y, v3.w, a1.w);
                    a2.x = fmaf(p.z, v3.x, a2.x); a2.y = fmaf(p.z, v3.y, a2.y);
                    a2.z = fmaf(p.z, v3.z, a2.z); a2.w = fmaf(p.z, v3.w, a2.w);
                    a3.x = fmaf(p.w, v3.x, a3.x); a3.y = fmaf(p.w, v3.y, a3.y);
                    a3.z = fmaf(p.w, v3.z, a3.z); a3.w = fmaf(p.w, v3.w, a3.w);
                }
            }
            *(float4*)&wacc[w][0][lane * 4] = a0;
            *(float4*)&wacc[w][1][lane * 4] = a1;
            *(float4*)&wacc[w][2][lane * 4] = a2;
            *(float4*)&wacc[w][3][lane * 4] = a3;
        }
        __syncthreads();

        // combine the 8 warps' partials and store (unnormalized)
        {
            const size_t pbase = ((size_t)bg * NB_NSPLIT + split) * NB_NREP;
            #pragma unroll
            for (int o = tid; o < NB_NREP * NB_HD; o += 256) {
                const int h = o >> 7, d = o & 127;
                float s = wacc[0][h][d];
                #pragma unroll
                for (int ww = 1; ww < 8; ww++) s += wacc[ww][h][d];
                g_pacc[(pbase + h) * NB_HD + d] = s;
            }
        }
        __threadfence();
    }
    __syncthreads();

    // ---- arrival + last-CTA-done reduction for this (b,g) ----
    if (tid == 0) s_old = atomicAdd(&g_cnt[bg], 1);
    __syncthreads();
    if (s_old != NB_NSPLIT - 1) return;

    __threadfence();   // acquire: observe all 16 CTAs' partials
    const int ns = min(NB_NSPLIT, (cl + NB_CHUNK - 1) >> 8);
    const size_t base = (size_t)bg * NB_NSPLIT * NB_NREP;

    if (tid < 4) {
        float M = -1e30f;
        for (int s = 0; s < ns; s++)
            M = fmaxf(M, g_pm[base + (size_t)s * NB_NREP + tid]);
        rM[tid] = M;
    }
    __syncthreads();
    if (tid < 64) {
        const int h = tid & 3, s = tid >> 2;
        rE[h][s] = (s < ns) ? __expf(g_pm[base + (size_t)s * NB_NREP + h] - rM[h]) : 0.f;
    }
    __syncthreads();
    if (tid < 4) {
        float L = 0.f;
        #pragma unroll
        for (int s = 0; s < NB_NSPLIT; s++)   // stale g_pl * e==0 contributes 0
            L = fmaf(g_pl[base + (size_t)s * NB_NREP + tid], rE[tid][s], L);
        rL[tid] = L;
    }
    __syncthreads();
    if (tid < 128) {
        const int h = tid >> 5, c = tid & 31;
        float4 o = make_float4(0.f, 0.f, 0.f, 0.f);
        #pragma unroll
        for (int s = 0; s < NB_NSPLIT; s++) { // stale g_pacc * e==0 contributes 0
            const float e = rE[h][s];
            const float4 a = *(const float4*)(g_pacc + (base + (size_t)s * NB_NREP + h) * NB_HD + c * 4);
            o.x = fmaf(a.x, e, o.x); o.y = fmaf(a.y, e, o.y);
            o.z = fmaf(a.z, e, o.z); o.w = fmaf(a.w, e, o.w);
        }
        const float inv = 1.f / rL[h];
        const size_t ob = ((size_t)(b * NB_NH + g * NB_NREP + h)) * NB_HD + c * 4;
        *(float4*)(out + ob) = make_float4(o.x * inv, o.y * inv, o.z * inv, o.w * inv);
    }
    if (tid == 0) g_cnt[bg] = 0;   // reset for next (graph) launch
}

extern "C" void kernel_launch(void* const* d_in, const int* in_sizes, int n_in,
                              void* d_out, int out_size)
{
    const float* q    = (const float*)d_in[0];
    const float* k    = (const float*)d_in[1];
    const float* v    = (const float*)d_in[2];
    const float* kc   = (const float*)d_in[3];
    const float* vc   = (const float*)d_in[4];
    const int*   bt   = (const int*)d_in[5];
    const int*   ctx  = (const int*)d_in[6];
    const int*   slot = (const int*)d_in[7];

    dim3 grid(NB_NSPLIT, NB_KVH, NB_BATCH);
    attn_split<<<grid, 256>>>(q, k, v, kc, vc, bt, ctx, slot, (float*)d_out);
}

// round 12
// speedup vs baseline: 1.5371x; 1.5371x over previous
#include <cuda_runtime.h>
#include <cuda_bf16.h>

#define NB_BATCH 16
#define NB_NH    32
#define NB_KVH   8
#define NB_NREP  4
#define NB_HD    128
#define NB_SCALE 0.08838834764831845f
#define NB_BPS   256
#define NB_NSPLIT 16
#define NB_CHUNK  256

// split-KV partial scratch (device globals: allocation-free)
__device__ float g_pacc[NB_BATCH * NB_KVH * NB_NSPLIT * NB_NREP * NB_HD]; // 4 MB
__device__ float g_pm[NB_BATCH * NB_KVH * NB_NSPLIT * NB_NREP];
__device__ float g_pl[NB_BATCH * NB_KVH * NB_NSPLIT * NB_NREP];
__device__ int   g_cnt[NB_BATCH * NB_KVH];   // zero-init; reset by reducer CTA

__global__ __launch_bounds__(256, 4) void attn_split(
    const float* __restrict__ q,
    const float* __restrict__ kn,
    const float* __restrict__ vn,
    const float* __restrict__ kc,
    const float* __restrict__ vc,
    const int* __restrict__ bt,
    const int* __restrict__ ctx,
    const int* __restrict__ slotmap,
    float* __restrict__ out)
{
    const int split = blockIdx.x, g = blockIdx.y, b = blockIdx.z;
    const int bg = b * NB_KVH + g;
    const int cl = ctx[b];
    const int j0 = split * NB_CHUNK;
    const bool active = (j0 < cl);

    __shared__ int   sbt[16];
    __shared__ int   sslot[16];
    __shared__ const float* kptr[NB_CHUNK];
    __shared__ const float* vptr[NB_CHUNK];
    __shared__ float4 sp[NB_CHUNK];
    __shared__ float wred[8][4];
    __shared__ float smx[4];
    __shared__ float wacc[8][NB_NREP][NB_HD];
    __shared__ int   s_old;
    __shared__ float rM[4], rL[4], rE[4][NB_NSPLIT];

    const int tid = threadIdx.x;
    const int w = tid >> 5, lane = tid & 31;

    if (active) {
        const int vcnt = min(NB_CHUNK, cl - j0);

        if (tid < 16) {
            sbt[tid]   = bt[b * NB_BPS + split * 16 + tid];
            sslot[tid] = slotmap[tid];
        }
        __syncthreads();
        {   // per-token resolved pointers — valid for ALL 256 t regardless of vcnt
            const int t = tid;
            const int s = sbt[t >> 4] * 16 + (t & 15);
            int ov = -1;
            #pragma unroll
            for (int bp = 0; bp < NB_BATCH; bp++)
                if (sslot[bp] == s) ov = bp;     // last match wins
            const size_t crow = ((size_t)s * NB_KVH + g) * NB_HD;
            const size_t nrow = ((size_t)((ov >= 0) ? ov : 0) * NB_KVH + g) * NB_HD;
            kptr[t] = (ov >= 0) ? (kn + nrow) : (kc + crow);
            vptr[t] = (ov >= 0) ? (vn + nrow) : (vc + crow);
        }
        __syncthreads();

        // uniform padded trip count (multiple of 4); overshoot tokens are
        // masked at softmax (e=0) so both passes run branch-free.
        const int nt4 = (((vcnt + 7) >> 3) + 3) & ~3;

        // ---- Pass 1: scores (K stream), double-buffered 4-batches ----
        {
            const float* qb = q + ((size_t)b * NB_NH + g * NB_NREP) * NB_HD + lane * 4;
            const float4 q0 = *(const float4*)(qb + 0 * NB_HD);
            const float4 q1 = *(const float4*)(qb + 1 * NB_HD);
            const float4 q2 = *(const float4*)(qb + 2 * NB_HD);
            const float4 q3 = *(const float4*)(qb + 3 * NB_HD);
            const bool b0 = (lane & 1) != 0;
            const bool b1 = (lane & 2) != 0;
            const int hm = ((lane & 1) << 1) | ((lane >> 1) & 1);

            float4 kk0 = *(const float4*)(kptr[0 * 8 + w] + lane * 4);
            float4 kk1 = *(const float4*)(kptr[1 * 8 + w] + lane * 4);
            float4 kk2 = *(const float4*)(kptr[2 * 8 + w] + lane * 4);
            float4 kk3 = *(const float4*)(kptr[3 * 8 + w] + lane * 4);

            #pragma unroll 1
            for (int i = 0; i < nt4; i += 4) {
                const int ip = (i + 4 < nt4) ? (i + 4) : 0;   // next group (safe wrap)
                // issue next group's loads FIRST (overlap with compute below)
                const float4 n0 = *(const float4*)(kptr[(ip + 0) * 8 + w] + lane * 4);
                const float4 n1 = *(const float4*)(kptr[(ip + 1) * 8 + w] + lane * 4);
                const float4 n2 = *(const float4*)(kptr[(ip + 2) * 8 + w] + lane * 4);
                const float4 n3 = *(const float4*)(kptr[(ip + 3) * 8 + w] + lane * 4);

                float bb[4];
                {
                    #pragma unroll
                    for (int j = 0; j < 4; j++) {
                        const float4 kk = (j == 0) ? kk0 : (j == 1) ? kk1 : (j == 2) ? kk2 : kk3;
                        float s0 = fmaf(q0.x, kk.x, fmaf(q0.y, kk.y, fmaf(q0.z, kk.z, q0.w * kk.w)));
                        float s1 = fmaf(q1.x, kk.x, fmaf(q1.y, kk.y, fmaf(q1.z, kk.z, q1.w * kk.w)));
                        float s2 = fmaf(q2.x, kk.x, fmaf(q2.y, kk.y, fmaf(q2.z, kk.z, q2.w * kk.w)));
                        float s3 = fmaf(q3.x, kk.x, fmaf(q3.y, kk.y, fmaf(q3.z, kk.z, q3.w * kk.w)));
                        // fold 4 heads into lane classes (keeps only bb[j] live)
                        float u  = b0 ? s0 : s2;
                        float vS = b0 ? s1 : s3;
                        float ru = __shfl_xor_sync(0xffffffffu, u, 1);
                        float rv = __shfl_xor_sync(0xffffffffu, vS, 1);
                        float a0 = (b0 ? s2 : s0) + ru;
                        float a1 = (b0 ? s3 : s1) + rv;
                        float ub = b1 ? a0 : a1;
                        float rb = __shfl_xor_sync(0xffffffffu, ub, 2);
                        bb[j] = (b1 ? a1 : a0) + rb;
                    }
                }
                #pragma unroll
                for (int j = 0; j < 4; j++) {
                    bb[j] += __shfl_xor_sync(0xffffffffu, bb[j], 4);
                    bb[j] += __shfl_xor_sync(0xffffffffu, bb[j], 8);
                    bb[j] += __shfl_xor_sync(0xffffffffu, bb[j], 16);
                }
                if (lane < 4) {
                    ((float*)&sp[(i + 0) * 8 + w])[hm] = bb[0] * NB_SCALE;
                    ((float*)&sp[(i + 1) * 8 + w])[hm] = bb[1] * NB_SCALE;
                    ((float*)&sp[(i + 2) * 8 + w])[hm] = bb[2] * NB_SCALE;
                    ((float*)&sp[(i + 3) * 8 + w])[hm] = bb[3] * NB_SCALE;
                }
                kk0 = n0; kk1 = n1; kk2 = n2; kk3 = n3;
            }
        }
        __syncthreads();

        // ---- Block softmax over the chunk ----
        {
            const int t = tid;
            float4 s4 = sp[t];
            if (t >= vcnt) { s4.x = s4.y = s4.z = s4.w = -1e30f; }
            float m0 = s4.x, m1 = s4.y, m2 = s4.z, m3 = s4.w;
            #pragma unroll
            for (int off = 16; off >= 1; off >>= 1) {
                m0 = fmaxf(m0, __shfl_xor_sync(0xffffffffu, m0, off));
                m1 = fmaxf(m1, __shfl_xor_sync(0xffffffffu, m1, off));
                m2 = fmaxf(m2, __shfl_xor_sync(0xffffffffu, m2, off));
                m3 = fmaxf(m3, __shfl_xor_sync(0xffffffffu, m3, off));
            }
            if (lane == 0) { wred[w][0] = m0; wred[w][1] = m1; wred[w][2] = m2; wred[w][3] = m3; }
            __syncthreads();
            if (tid < 4) {
                float mm = wred[0][tid];
                #pragma unroll
                for (int ww = 1; ww < 8; ww++) mm = fmaxf(mm, wred[ww][tid]);
                smx[tid] = mm;
            }
            __syncthreads();
            const float M0 = smx[0], M1 = smx[1], M2 = smx[2], M3 = smx[3];
            float e0 = 0.f, e1 = 0.f, e2 = 0.f, e3 = 0.f;
            if (t < vcnt) {
                e0 = __expf(s4.x - M0); e1 = __expf(s4.y - M1);
                e2 = __expf(s4.z - M2); e3 = __expf(s4.w - M3);
            }
            sp[t] = make_float4(e0, e1, e2, e3);
            #pragma unroll
            for (int off = 16; off >= 1; off >>= 1) {
                e0 += __shfl_xor_sync(0xffffffffu, e0, off);
                e1 += __shfl_xor_sync(0xffffffffu, e1, off);
                e2 += __shfl_xor_sync(0xffffffffu, e2, off);
                e3 += __shfl_xor_sync(0xffffffffu, e3, off);
            }
            if (lane == 0) { wred[w][0] = e0; wred[w][1] = e1; wred[w][2] = e2; wred[w][3] = e3; }
            __syncthreads();
            if (tid < 4) {
                float ss = wred[0][tid];
                #pragma unroll
                for (int ww = 1; ww < 8; ww++) ss += wred[ww][tid];
                const size_t pidx = ((size_t)bg * NB_NSPLIT + split) * NB_NREP + tid;
                g_pm[pidx] = smx[tid];
                g_pl[pidx] = ss;
            }
            __syncthreads();
        }

        // ---- Pass 2: output accumulation (V stream), double-buffered ----
        {
            float4 a0 = make_float4(0.f,0.f,0.f,0.f), a1 = a0, a2 = a0, a3 = a0;

            float4 vv0 = *(const float4*)(vptr[0 * 8 + w] + lane * 4);
            float4 vv1 = *(const float4*)(vptr[1 * 8 + w] + lane * 4);
            float4 vv2 = *(const float4*)(vptr[2 * 8 + w] + lane * 4);
            float4 vv3 = *(const float4*)(vptr[3 * 8 + w] + lane * 4);

            #pragma unroll 1
            for (int i = 0; i < nt4; i += 4) {
                const int ip = (i + 4 < nt4) ? (i + 4) : 0;
                const float4 n0 = *(const float4*)(vptr[(ip + 0) * 8 + w] + lane * 4);
                const float4 n1 = *(const float4*)(vptr[(ip + 1) * 8 + w] + lane * 4);
                const float4 n2 = *(const float4*)(vptr[(ip + 2) * 8 + w] + lane * 4);
                const float4 n3 = *(const float4*)(vptr[(ip + 3) * 8 + w] + lane * 4);
                {
                    const float4 p = sp[(i + 0) * 8 + w];
                    a0.x = fmaf(p.x, vv0.x, a0.x); a0.y = fmaf(p.x, vv0.y, a0.y);
                    a0.z = fmaf(p.x, vv0.z, a0.z); a0.w = fmaf(p.x, vv0.w, a0.w);
                    a1.x = fmaf(p.y, vv0.x, a1.x); a1.y = fmaf(p.y, vv0.y, a1.y);
                    a1.z = fmaf(p.y, vv0.z, a1.z); a1.w = fmaf(p.y, vv0.w, a1.w);
                    a2.x = fmaf(p.z, vv0.x, a2.x); a2.y = fmaf(p.z, vv0.y, a2.y);
                    a2.z = fmaf(p.z, vv0.z, a2.z); a2.w = fmaf(p.z, vv0.w, a2.w);
                    a3.x = fmaf(p.w, vv0.x, a3.x); a3.y = fmaf(p.w, vv0.y, a3.y);
                    a3.z = fmaf(p.w, vv0.z, a3.z); a3.w = fmaf(p.w, vv0.w, a3.w);
                }
                {
                    const float4 p = sp[(i + 1) * 8 + w];
                    a0.x = fmaf(p.x, vv1.x, a0.x); a0.y = fmaf(p.x, vv1.y, a0.y);
                    a0.z = fmaf(p.x, vv1.z, a0.z); a0.w = fmaf(p.x, vv1.w, a0.w);
                    a1.x = fmaf(p.y, vv1.x, a1.x); a1.y = fmaf(p.y, vv1.y, a1.y);
                    a1.z = fmaf(p.y, vv1.z, a1.z); a1.w = fmaf(p.y, vv1.w, a1.w);
                    a2.x = fmaf(p.z, vv1.x, a2.x); a2.y = fmaf(p.z, vv1.y, a2.y);
                    a2.z = fmaf(p.z, vv1.z, a2.z); a2.w = fmaf(p.z, vv1.w, a2.w);
                    a3.x = fmaf(p.w, vv1.x, a3.x); a3.y = fmaf(p.w, vv1.y, a3.y);
                    a3.z = fmaf(p.w, vv1.z, a3.z); a3.w = fmaf(p.w, vv1.w, a3.w);
                }
                {
                    const float4 p = sp[(i + 2) * 8 + w];
                    a0.x = fmaf(p.x, vv2.x, a0.x); a0.y = fmaf(p.x, vv2.y, a0.y);
                    a0.z = fmaf(p.x, vv2.z, a0.z); a0.w = fmaf(p.x, vv2.w, a0.w);
                    a1.x = fmaf(p.y, vv2.x, a1.x); a1.y = fmaf(p.y, vv2.y, a1.y);
                    a1.z = fmaf(p.y, vv2.z, a1.z); a1.w = fmaf(p.y, vv2.w, a1.w);
                    a2.x = fmaf(p.z, vv2.x, a2.x); a2.y = fmaf(p.z, vv2.y, a2.y);
                    a2.z = fmaf(p.z, vv2.z, a2.z); a2.w = fmaf(p.z, vv2.w, a2.w);
                    a3.x = fmaf(p.w, vv2.x, a3.x); a3.y = fmaf(p.w, vv2.y, a3.y);
                    a3.z = fmaf(p.w, vv2.z, a3.z); a3.w = fmaf(p.w, vv2.w, a3.w);
                }
                {
                    const float4 p = sp[(i + 3) * 8 + w];
                    a0.x = fmaf(p.x, vv3.x, a0.x); a0.y = fmaf(p.x, vv3.y, a0.y);
                    a0.z = fmaf(p.x, vv3.z, a0.z); a0.w = fmaf(p.x, vv3.w, a0.w);
                    a1.x = fmaf(p.y, vv3.x, a1.x); a1.y = fmaf(p.y, vv3.y, a1.y);
                    a1.z = fmaf(p.y, vv3.z, a1.z); a1.w = fmaf(p.y, vv3.w, a1.w);
                    a2.x = fmaf(p.z, vv3.x, a2.x); a2.y = fmaf(p.z, vv3.y, a2.y);
                    a2.z = fmaf(p.z, vv3.z, a2.z); a2.w = fmaf(p.z, vv3.w, a2.w);
                    a3.x = fmaf(p.w, vv3.x, a3.x); a3.y = fmaf(p.w, vv3.y, a3.y);
                    a3.z = fmaf(p.w, vv3.z, a3.z); a3.w = fmaf(p.w, vv3.w, a3.w);
                }
                vv0 = n0; vv1 = n1; vv2 = n2; vv3 = n3;
            }
            *(float4*)&wacc[w][0][lane * 4] = a0;
            *(float4*)&wacc[w][1][lane * 4] = a1;
            *(float4*)&wacc[w][2][lane * 4] = a2;
            *(float4*)&wacc[w][3][lane * 4] = a3;
        }
        __syncthreads();

        // combine the 8 warps' partials and store (unnormalized)
        {
            const size_t pbase = ((size_t)bg * NB_NSPLIT + split) * NB_NREP;
            #pragma unroll
            for (int o = tid; o < NB_NREP * NB_HD; o += 256) {
                const int h = o >> 7, d = o & 127;
                float s = wacc[0][h][d];
                #pragma unroll
                for (int ww = 1; ww < 8; ww++) s += wacc[ww][h][d];
                g_pacc[(pbase + h) * NB_HD + d] = s;
            }
        }
        __threadfence();
    }
    __syncthreads();

    // ---- arrival + last-CTA-done reduction for this (b,g) ----
    if (tid == 0) s_old = atomicAdd(&g_cnt[bg], 1);
    __syncthreads();
    if (s_old != NB_NSPLIT - 1) return;

    __threadfence();   // acquire: observe all 16 CTAs' partials
    const int ns = min(NB_NSPLIT, (cl + NB_CHUNK - 1) >> 8);
    const size_t base = (size_t)bg * NB_NSPLIT * NB_NREP;

    if (tid < 4) {
        float M = -1e30f;
        for (int s = 0; s < ns; s++)
            M = fmaxf(M, g_pm[base + (size_t)s * NB_NREP + tid]);
        rM[tid] = M;
    }
    __syncthreads();
    if (tid < 64) {
        const int h = tid & 3, s = tid >> 2;
        rE[h][s] = (s < ns) ? __expf(g_pm[base + (size_t)s * NB_NREP + h] - rM[h]) : 0.f;
    }
    __syncthreads();
    if (tid < 4) {
        float L = 0.f;
        #pragma unroll
        for (int s = 0; s < NB_NSPLIT; s++)   // stale g_pl * e==0 contributes 0
            L = fmaf(g_pl[base + (size_t)s * NB_NREP + tid], rE[tid][s], L);
        rL[tid] = L;
    }
    __syncthreads();
    if (tid < 128) {
        const int h = tid >> 5, c = tid & 31;
        float4 o = make_float4(0.f, 0.f, 0.f, 0.f);
        #pragma unroll
        for (int s = 0; s < NB_NSPLIT; s++) { // stale g_pacc * e==0 contributes 0
            const float e = rE[h][s];
            const float4 a = *(const float4*)(g_pacc + (base + (size_t)s * NB_NREP + h) * NB_HD + c * 4);
            o.x = fmaf(a.x, e, o.x); o.y = fmaf(a.y, e, o.y);
            o.z = fmaf(a.z, e, o.z); o.w = fmaf(a.w, e, o.w);
        }
        const float inv = 1.f / rL[h];
        const size_t ob = ((size_t)(b * NB_NH + g * NB_NREP + h)) * NB_HD + c * 4;
        *(float4*)(out + ob) = make_float4(o.x * inv, o.y * inv, o.z * inv, o.w * inv);
    }
    if (tid == 0) g_cnt[bg] = 0;   // reset for next (graph) launch
}

extern "C" void kernel_launch(void* const* d_in, const int* in_sizes, int n_in,
                              void* d_out, int out_size)
{
    const float* q    = (const float*)d_in[0];
    const float* k    = (const float*)d_in[1];
    const float* v    = (const float*)d_in[2];
    const float* kc   = (const float*)d_in[3];
    const float* vc   = (const float*)d_in[4];
    const int*   bt   = (const int*)d_in[5];
    const int*   ctx  = (const int*)d_in[6];
    const int*   slot = (const int*)d_in[7];

    dim3 grid(NB_NSPLIT, NB_KVH, NB_BATCH);
    attn_split<<<grid, 256>>>(q, k, v, kc, vc, bt, ctx, slot, (float*)d_out);
}

// round 15
// speedup vs baseline: 1.5511x; 1.0091x over previous
#include <cuda_runtime.h>
#include <cuda_bf16.h>

#define NB_BATCH 16
#define NB_NH    32
#define NB_KVH   8
#define NB_NREP  4
#define NB_HD    128
#define NB_SCALE 0.08838834764831845f
#define NB_BPS   256
#define NB_NSPLIT 16
#define NB_CHUNK  256

// split-KV partial scratch (device globals: allocation-free)
__device__ float g_pacc[NB_BATCH * NB_KVH * NB_NSPLIT * NB_NREP * NB_HD]; // 4 MB
__device__ float g_pm[NB_BATCH * NB_KVH * NB_NSPLIT * NB_NREP];
__device__ float g_pl[NB_BATCH * NB_KVH * NB_NSPLIT * NB_NREP];
__device__ int   g_cnt[NB_BATCH * NB_KVH];   // zero-init; reset by reducer CTA

// packed f32x2 dot: (q.x*k.x+q.z*k.z) + (q.y*k.y+q.w*k.w)  [FFMA2 path]
__device__ __forceinline__ float dot4_p(const float4 qv, const float4 kv) {
    float lo, hi;
    asm("{\n\t"
        ".reg .b64 qa,qb,ka,kb,t,r;\n\t"
        "mov.b64 qa, {%2,%3};\n\t"
        "mov.b64 qb, {%4,%5};\n\t"
        "mov.b64 ka, {%6,%7};\n\t"
        "mov.b64 kb, {%8,%9};\n\t"
        "mul.rn.f32x2 t, qb, kb;\n\t"
        "fma.rn.f32x2 r, qa, ka, t;\n\t"
        "mov.b64 {%0,%1}, r;\n\t"
        "}"
        : "=f"(lo), "=f"(hi)
        : "f"(qv.x), "f"(qv.y), "f"(qv.z), "f"(qv.w),
          "f"(kv.x), "f"(kv.y), "f"(kv.z), "f"(kv.w));
    return lo + hi;
}

// packed f32x2 acc: a += p * v (4 wide, 2x FFMA2) — "+f" read-write operands
__device__ __forceinline__ void fma4_p(float4& a, const float p, const float4 vv) {
    asm("{\n\t"
        ".reg .b64 pp,v01,v23,a01,a23;\n\t"
        "mov.b64 pp,  {%4,%4};\n\t"
        "mov.b64 v01, {%5,%6};\n\t"
        "mov.b64 v23, {%7,%8};\n\t"
        "mov.b64 a01, {%0,%1};\n\t"
        "mov.b64 a23, {%2,%3};\n\t"
        "fma.rn.f32x2 a01, pp, v01, a01;\n\t"
        "fma.rn.f32x2 a23, pp, v23, a23;\n\t"
        "mov.b64 {%0,%1}, a01;\n\t"
        "mov.b64 {%2,%3}, a23;\n\t"
        "}"
        : "+f"(a.x), "+f"(a.y), "+f"(a.z), "+f"(a.w)
        : "f"(p), "f"(vv.x), "f"(vv.y), "f"(vv.z), "f"(vv.w));
}

__global__ __launch_bounds__(256, 4) void attn_split(
    const float* __restrict__ q,
    const float* __restrict__ kn,
    const float* __restrict__ vn,
    const float* __restrict__ kc,
    const float* __restrict__ vc,
    const int* __restrict__ bt,
    const int* __restrict__ ctx,
    const int* __restrict__ slotmap,
    float* __restrict__ out)
{
    const int split = blockIdx.x, g = blockIdx.y, b = blockIdx.z;
    const int bg = b * NB_KVH + g;
    const int cl = ctx[b];
    const int j0 = split * NB_CHUNK;
    const bool active = (j0 < cl);

    __shared__ int   sbt[16];
    __shared__ int   sslot[16];
    __shared__ const float* kptr[NB_CHUNK];
    __shared__ const float* vptr[NB_CHUNK];
    __shared__ float4 sp[NB_CHUNK];
    __shared__ float wred[8][4];
    __shared__ float smx[4];
    __shared__ float wacc[8][NB_NREP][NB_HD];
    __shared__ int   s_old;
    __shared__ float rM[4], rL[4], rE[4][NB_NSPLIT];

    const int tid = threadIdx.x;
    const int w = tid >> 5, lane = tid & 31;

    if (active) {
        const int vcnt = min(NB_CHUNK, cl - j0);

        if (tid < 16) {
            sbt[tid]   = bt[b * NB_BPS + split * 16 + tid];
            sslot[tid] = slotmap[tid];
        }
        __syncthreads();
        {   // per-token resolved pointers — valid for ALL 256 t regardless of vcnt
            const int t = tid;
            const int s = sbt[t >> 4] * 16 + (t & 15);
            int ov = -1;
            #pragma unroll
            for (int bp = 0; bp < NB_BATCH; bp++)
                if (sslot[bp] == s) ov = bp;     // last match wins
            const size_t crow = ((size_t)s * NB_KVH + g) * NB_HD;
            const size_t nrow = ((size_t)((ov >= 0) ? ov : 0) * NB_KVH + g) * NB_HD;
            kptr[t] = (ov >= 0) ? (kn + nrow) : (kc + crow);
            vptr[t] = (ov >= 0) ? (vn + nrow) : (vc + crow);
        }
        __syncthreads();

        // uniform padded trip count (multiple of 4); overshoot tokens are
        // masked at softmax (e=0) so both passes run branch-free.
        const int nt4 = (((vcnt + 7) >> 3) + 3) & ~3;

        // ---- Pass 1: scores (K stream), double-buffered 4-batches ----
        {
            const float* qb = q + ((size_t)b * NB_NH + g * NB_NREP) * NB_HD + lane * 4;
            const float4 q0 = *(const float4*)(qb + 0 * NB_HD);
            const float4 q1 = *(const float4*)(qb + 1 * NB_HD);
            const float4 q2 = *(const float4*)(qb + 2 * NB_HD);
            const float4 q3 = *(const float4*)(qb + 3 * NB_HD);
            const bool b0 = (lane & 1) != 0;
            const bool b1 = (lane & 2) != 0;
            const int hm = ((lane & 1) << 1) | ((lane >> 1) & 1);

            float4 kk0 = *(const float4*)(kptr[0 * 8 + w] + lane * 4);
            float4 kk1 = *(const float4*)(kptr[1 * 8 + w] + lane * 4);
            float4 kk2 = *(const float4*)(kptr[2 * 8 + w] + lane * 4);
            float4 kk3 = *(const float4*)(kptr[3 * 8 + w] + lane * 4);

            #pragma unroll 1
            for (int i = 0; i < nt4; i += 4) {
                const int ip = (i + 4 < nt4) ? (i + 4) : 0;   // next group (safe wrap)
                // issue next group's loads FIRST (overlap with compute below)
                const float4 n0 = *(const float4*)(kptr[(ip + 0) * 8 + w] + lane * 4);
                const float4 n1 = *(const float4*)(kptr[(ip + 1) * 8 + w] + lane * 4);
                const float4 n2 = *(const float4*)(kptr[(ip + 2) * 8 + w] + lane * 4);
                const float4 n3 = *(const float4*)(kptr[(ip + 3) * 8 + w] + lane * 4);

                float bb[4];
                {
                    #pragma unroll
                    for (int j = 0; j < 4; j++) {
                        const float4 kk = (j == 0) ? kk0 : (j == 1) ? kk1 : (j == 2) ? kk2 : kk3;
                        float s0 = dot4_p(q0, kk);
                        float s1 = dot4_p(q1, kk);
                        float s2 = dot4_p(q2, kk);
                        float s3 = dot4_p(q3, kk);
                        // fold 4 heads into lane classes (keeps only bb[j] live)
                        float u  = b0 ? s0 : s2;
                        float vS = b0 ? s1 : s3;
                        float ru = __shfl_xor_sync(0xffffffffu, u, 1);
                        float rv = __shfl_xor_sync(0xffffffffu, vS, 1);
                        float a0 = (b0 ? s2 : s0) + ru;
                        float a1 = (b0 ? s3 : s1) + rv;
                        float ub = b1 ? a0 : a1;
                        float rb = __shfl_xor_sync(0xffffffffu, ub, 2);
                        bb[j] = (b1 ? a1 : a0) + rb;
                    }
                }
                #pragma unroll
                for (int j = 0; j < 4; j++) {
                    bb[j] += __shfl_xor_sync(0xffffffffu, bb[j], 4);
                    bb[j] += __shfl_xor_sync(0xffffffffu, bb[j], 8);
                    bb[j] += __shfl_xor_sync(0xffffffffu, bb[j], 16);
                }
                if (lane < 4) {
                    ((float*)&sp[(i + 0) * 8 + w])[hm] = bb[0] * NB_SCALE;
                    ((float*)&sp[(i + 1) * 8 + w])[hm] = bb[1] * NB_SCALE;
                    ((float*)&sp[(i + 2) * 8 + w])[hm] = bb[2] * NB_SCALE;
                    ((float*)&sp[(i + 3) * 8 + w])[hm] = bb[3] * NB_SCALE;
                }
                kk0 = n0; kk1 = n1; kk2 = n2; kk3 = n3;
            }
        }
        __syncthreads();

        // ---- Block softmax over the chunk ----
        {
            const int t = tid;
            float4 s4 = sp[t];
            if (t >= vcnt) { s4.x = s4.y = s4.z = s4.w = -1e30f; }
            float m0 = s4.x, m1 = s4.y, m2 = s4.z, m3 = s4.w;
            #pragma unroll
            for (int off = 16; off >= 1; off >>= 1) {
                m0 = fmaxf(m0, __shfl_xor_sync(0xffffffffu, m0, off));
                m1 = fmaxf(m1, __shfl_xor_sync(0xffffffffu, m1, off));
                m2 = fmaxf(m2, __shfl_xor_sync(0xffffffffu, m2, off));
                m3 = fmaxf(m3, __shfl_xor_sync(0xffffffffu, m3, off));
            }
            if (lane == 0) { wred[w][0] = m0; wred[w][1] = m1; wred[w][2] = m2; wred[w][3] = m3; }
            __syncthreads();
            if (tid < 4) {
                float mm = wred[0][tid];
                #pragma unroll
                for (int ww = 1; ww < 8; ww++) mm = fmaxf(mm, wred[ww][tid]);
                smx[tid] = mm;
            }
            __syncthreads();
            const float M0 = smx[0], M1 = smx[1], M2 = smx[2], M3 = smx[3];
            float e0 = 0.f, e1 = 0.f, e2 = 0.f, e3 = 0.f;
            if (t < vcnt) {
                e0 = __expf(s4.x - M0); e1 = __expf(s4.y - M1);
                e2 = __expf(s4.z - M2); e3 = __expf(s4.w - M3);
            }
            sp[t] = make_float4(e0, e1, e2, e3);
            #pragma unroll
            for (int off = 16; off >= 1; off >>= 1) {
                e0 += __shfl_xor_sync(0xffffffffu, e0, off);
                e1 += __shfl_xor_sync(0xffffffffu, e1, off);
                e2 += __shfl_xor_sync(0xffffffffu, e2, off);
                e3 += __shfl_xor_sync(0xffffffffu, e3, off);
            }
            if (lane == 0) { wred[w][0] = e0; wred[w][1] = e1; wred[w][2] = e2; wred[w][3] = e3; }
            __syncthreads();
            if (tid < 4) {
                float ss = wred[0][tid];
                #pragma unroll
                for (int ww = 1; ww < 8; ww++) ss += wred[ww][tid];
                const size_t pidx = ((size_t)bg * NB_NSPLIT + split) * NB_NREP + tid;
                g_pm[pidx] = smx[tid];
                g_pl[pidx] = ss;
            }
            __syncthreads();
        }

        // ---- Pass 2: output accumulation (V stream), double-buffered ----
        {
            float4 a0 = make_float4(0.f,0.f,0.f,0.f), a1 = a0, a2 = a0, a3 = a0;

            float4 vv0 = *(const float4*)(vptr[0 * 8 + w] + lane * 4);
            float4 vv1 = *(const float4*)(vptr[1 * 8 + w] + lane * 4);
            float4 vv2 = *(const float4*)(vptr[2 * 8 + w] + lane * 4);
            float4 vv3 = *(const float4*)(vptr[3 * 8 + w] + lane * 4);

            #pragma unroll 1
            for (int i = 0; i < nt4; i += 4) {
                const int ip = (i + 4 < nt4) ? (i + 4) : 0;
                const float4 n0 = *(const float4*)(vptr[(ip + 0) * 8 + w] + lane * 4);
                const float4 n1 = *(const float4*)(vptr[(ip + 1) * 8 + w] + lane * 4);
                const float4 n2 = *(const float4*)(vptr[(ip + 2) * 8 + w] + lane * 4);
                const float4 n3 = *(const float4*)(vptr[(ip + 3) * 8 + w] + lane * 4);
                {
                    const float4 p = sp[(i + 0) * 8 + w];
                    fma4_p(a0, p.x, vv0); fma4_p(a1, p.y, vv0);
                    fma4_p(a2, p.z, vv0); fma4_p(a3, p.w, vv0);
                }
                {
                    const float4 p = sp[(i + 1) * 8 + w];
                    fma4_p(a0, p.x, vv1); fma4_p(a1, p.y, vv1);
                    fma4_p(a2, p.z, vv1); fma4_p(a3, p.w, vv1);
                }
                {
                    const float4 p = sp[(i + 2) * 8 + w];
                    fma4_p(a0, p.x, vv2); fma4_p(a1, p.y, vv2);
                    fma4_p(a2, p.z, vv2); fma4_p(a3, p.w, vv2);
                }
                {
                    const float4 p = sp[(i + 3) * 8 + w];
                    fma4_p(a0, p.x, vv3); fma4_p(a1, p.y, vv3);
                    fma4_p(a2, p.z, vv3); fma4_p(a3, p.w, vv3);
                }
                vv0 = n0; vv1 = n1; vv2 = n2; vv3 = n3;
            }
            *(float4*)&wacc[w][0][lane * 4] = a0;
            *(float4*)&wacc[w][1][lane * 4] = a1;
            *(float4*)&wacc[w][2][lane * 4] = a2;
            *(float4*)&wacc[w][3][lane * 4] = a3;
        }
        __syncthreads();

        // combine the 8 warps' partials and store (unnormalized)
        {
            const size_t pbase = ((size_t)bg * NB_NSPLIT + split) * NB_NREP;
            #pragma unroll
            for (int o = tid; o < NB_NREP * NB_HD; o += 256) {
                const int h = o >> 7, d = o & 127;
                float s = wacc[0][h][d];
                #pragma unroll
                for (int ww = 1; ww < 8; ww++) s += wacc[ww][h][d];
                g_pacc[(pbase + h) * NB_HD + d] = s;
            }
        }
        __threadfence();
    }
    __syncthreads();

    // ---- arrival + last-CTA-done reduction for this (b,g) ----
    if (tid == 0) s_old = atomicAdd(&g_cnt[bg], 1);
    __syncthreads();
    if (s_old != NB_NSPLIT - 1) return;

    __threadfence();   // acquire: observe all 16 CTAs' partials
    const int ns = min(NB_NSPLIT, (cl + NB_CHUNK - 1) >> 8);
    const size_t base = (size_t)bg * NB_NSPLIT * NB_NREP;

    if (tid < 4) {
        float M = -1e30f;
        for (int s = 0; s < ns; s++)
            M = fmaxf(M, g_pm[base + (size_t)s * NB_NREP + tid]);
        rM[tid] = M;
    }
    __syncthreads();
    if (tid < 64) {
        const int h = tid & 3, s = tid >> 2;
        rE[h][s] = (s < ns) ? __expf(g_pm[base + (size_t)s * NB_NREP + h] - rM[h]) : 0.f;
    }
    __syncthreads();
    if (tid < 4) {
        float L = 0.f;
        #pragma unroll
        for (int s = 0; s < NB_NSPLIT; s++)   // stale g_pl * e==0 contributes 0
            L = fmaf(g_pl[base + (size_t)s * NB_NREP + tid], rE[tid][s], L);
        rL[tid] = L;
    }
    __syncthreads();
    if (tid < 128) {
        const int h = tid >> 5, c = tid & 31;
        float4 o = make_float4(0.f, 0.f, 0.f, 0.f);
        #pragma unroll
        for (int s = 0; s < NB_NSPLIT; s++) { // stale g_pacc * e==0 contributes 0
            const float e = rE[h][s];
            const float4 a = *(const float4*)(g_pacc + (base + (size_t)s * NB_NREP + h) * NB_HD + c * 4);
            fma4_p(o, e, a);
        }
        const float inv = 1.f / rL[h];
        const size_t ob = ((size_t)(b * NB_NH + g * NB_NREP + h)) * NB_HD + c * 4;
        *(float4*)(out + ob) = make_float4(o.x * inv, o.y * inv, o.z * inv, o.w * inv);
    }
    if (tid == 0) g_cnt[bg] = 0;   // reset for next (graph) launch
}

extern "C" void kernel_launch(void* const* d_in, const int* in_sizes, int n_in,
                              void* d_out, int out_size)
{
    const float* q    = (const float*)d_in[0];
    const float* k    = (const float*)d_in[1];
    const float* v    = (const float*)d_in[2];
    const float* kc   = (const float*)d_in[3];
    const float* vc   = (const float*)d_in[4];
    const int*   bt   = (const int*)d_in[5];
    const int*   ctx  = (const int*)d_in[6];
    const int*   slot = (const int*)d_in[7];

    dim3 grid(NB_NSPLIT, NB_KVH, NB_BATCH);
    attn_split<<<grid, 256>>>(q, k, v, kc, vc, bt, ctx, slot, (float*)d_out);
}